// round 2
// baseline (speedup 1.0000x reference)
#include <cuda_runtime.h>
#include <cuda_bf16.h>
#include <cstdint>

#define N_NODES 50000
#define N_EDGES 600000
#define HID     128
#define N_GRAPHS 512
#define BN_EPS  1e-5f

// ---------------- scratch (static device allocations; no cudaMalloc) ----------------
__device__ float g_h0[N_NODES * HID];
__device__ float g_t1[N_NODES * HID];
__device__ float g_h1[N_NODES * HID];
__device__ float g_hbn[N_NODES * HID];
__device__ float g_neigh[N_NODES * HID];

__device__ int   g_deg[N_NODES];
__device__ int   g_off[N_NODES + 1];
__device__ int   g_cur[N_NODES];
__device__ int   g_csr[N_EDGES];
__device__ float g_invdeg[N_NODES];

__device__ float g_bnsum[HID];
__device__ float g_bnsq[HID];
__device__ float g_scale[HID];
__device__ float g_shift[HID];

// ---------------- setup kernels ----------------
__global__ void zero_init_kernel() {
    int i = blockIdx.x * blockDim.x + threadIdx.x;
    if (i < N_NODES) g_deg[i] = 0;
    if (i < HID) { g_bnsum[i] = 0.f; g_bnsq[i] = 0.f; }
}

__global__ void hist_kernel(const int* __restrict__ dst) {
    int e = blockIdx.x * blockDim.x + threadIdx.x;
    if (e < N_EDGES) atomicAdd(&g_deg[dst[e]], 1);
}

// single-block exclusive scan over degrees -> offsets, cursor, inv_deg
__global__ void scan_kernel() {
    __shared__ int sh[1024];
    const int CH = (N_NODES + 1023) / 1024;  // 49
    int t = threadIdx.x;
    int base = t * CH;
    int tsum = 0;
    for (int i = 0; i < CH; i++) {
        int idx = base + i;
        if (idx < N_NODES) tsum += g_deg[idx];
    }
    sh[t] = tsum;
    __syncthreads();
    for (int off = 1; off < 1024; off <<= 1) {
        int v = (t >= off) ? sh[t - off] : 0;
        __syncthreads();
        sh[t] += v;
        __syncthreads();
    }
    int run = sh[t] - tsum;  // exclusive prefix
    for (int i = 0; i < CH; i++) {
        int idx = base + i;
        if (idx < N_NODES) {
            int d = g_deg[idx];
            g_off[idx] = run;
            g_cur[idx] = run;
            g_invdeg[idx] = 1.0f / (float)max(d, 1);
            run += d;
        }
    }
    if (t == 1023) g_off[N_NODES] = sh[1023];
}

__global__ void scatter_kernel(const int* __restrict__ src, const int* __restrict__ dst) {
    int e = blockIdx.x * blockDim.x + threadIdx.x;
    if (e < N_EDGES) {
        int d = dst[e];
        int p = atomicAdd(&g_cur[d], 1);
        g_csr[p] = src[e];
    }
}

// ---------------- aggregation kernels (warp per node) ----------------
__global__ void gin_agg_kernel(const float* __restrict__ x) {
    int w = (blockIdx.x * blockDim.x + threadIdx.x) >> 5;
    int lane = threadIdx.x & 31;
    if (w >= N_NODES) return;
    const float4* x4 = (const float4*)x;
    float4 acc = __ldg(&x4[w * 32 + lane]);  // self (GIN eps=0: x + sum)
    int e = g_off[w], end = g_off[w + 1];
    for (; e + 4 <= end; e += 4) {
        int s0 = g_csr[e + 0], s1 = g_csr[e + 1], s2 = g_csr[e + 2], s3 = g_csr[e + 3];
        float4 v0 = __ldg(&x4[s0 * 32 + lane]);
        float4 v1 = __ldg(&x4[s1 * 32 + lane]);
        float4 v2 = __ldg(&x4[s2 * 32 + lane]);
        float4 v3 = __ldg(&x4[s3 * 32 + lane]);
        acc.x += v0.x + v1.x + v2.x + v3.x;
        acc.y += v0.y + v1.y + v2.y + v3.y;
        acc.z += v0.z + v1.z + v2.z + v3.z;
        acc.w += v0.w + v1.w + v2.w + v3.w;
    }
    for (; e < end; e++) {
        int s0 = g_csr[e];
        float4 v0 = __ldg(&x4[s0 * 32 + lane]);
        acc.x += v0.x; acc.y += v0.y; acc.z += v0.z; acc.w += v0.w;
    }
    ((float4*)g_h0)[w * 32 + lane] = acc;
}

__device__ __forceinline__ float4 bn_relu4(float4 h, float4 sc, float4 sh) {
    float4 r;
    r.x = fmaxf(fmaf(h.x, sc.x, sh.x), 0.f);
    r.y = fmaxf(fmaf(h.y, sc.y, sh.y), 0.f);
    r.z = fmaxf(fmaf(h.z, sc.z, sh.z), 0.f);
    r.w = fmaxf(fmaf(h.w, sc.w, sh.w), 0.f);
    return r;
}

__global__ void sage_agg_kernel(const float* __restrict__ hraw,
                                float* __restrict__ hbn,
                                float* __restrict__ neigh) {
    int w = (blockIdx.x * blockDim.x + threadIdx.x) >> 5;
    int lane = threadIdx.x & 31;
    if (w >= N_NODES) return;
    float4 sc = *(const float4*)&g_scale[lane * 4];
    float4 sh = *(const float4*)&g_shift[lane * 4];
    const float4* h4 = (const float4*)hraw;

    float4 self = bn_relu4(__ldg(&h4[w * 32 + lane]), sc, sh);
    ((float4*)hbn)[w * 32 + lane] = self;

    float4 acc = make_float4(0.f, 0.f, 0.f, 0.f);
    int e = g_off[w], end = g_off[w + 1];
    for (; e + 4 <= end; e += 4) {
        int s0 = g_csr[e + 0], s1 = g_csr[e + 1], s2 = g_csr[e + 2], s3 = g_csr[e + 3];
        float4 v0 = bn_relu4(__ldg(&h4[s0 * 32 + lane]), sc, sh);
        float4 v1 = bn_relu4(__ldg(&h4[s1 * 32 + lane]), sc, sh);
        float4 v2 = bn_relu4(__ldg(&h4[s2 * 32 + lane]), sc, sh);
        float4 v3 = bn_relu4(__ldg(&h4[s3 * 32 + lane]), sc, sh);
        acc.x += v0.x + v1.x + v2.x + v3.x;
        acc.y += v0.y + v1.y + v2.y + v3.y;
        acc.z += v0.z + v1.z + v2.z + v3.z;
        acc.w += v0.w + v1.w + v2.w + v3.w;
    }
    for (; e < end; e++) {
        int s0 = g_csr[e];
        float4 v0 = bn_relu4(__ldg(&h4[s0 * 32 + lane]), sc, sh);
        acc.x += v0.x; acc.y += v0.y; acc.z += v0.z; acc.w += v0.w;
    }
    float id = g_invdeg[w];
    acc.x *= id; acc.y *= id; acc.z *= id; acc.w *= id;
    ((float4*)neigh)[w * 32 + lane] = acc;
}

// ---------------- tensor-core GEMM (tf32x3 split precision) ----------------
// out[M,128] = sum_parts A_p[M,128] @ W_p[128,128] + bias, optional relu / BN stats.
// Block: 256 threads = 8 warps (4 along M x 2 along N). Tile: 128 rows x 128 cols.
// Warp tile: 32 rows x 64 cols = 2 m-tiles x 8 n-tiles of m16n8k8.
// K staged in chunks of 16 with hi/lo tf32 split (error ~2^-21, fp32-like).

#define KC 16
#define APAD 20   // smem row stride (floats) for A tiles
#define BPAD 132  // smem row stride (floats) for B tiles

__device__ __forceinline__ void tf32_split(float v, uint32_t& hi, uint32_t& lo) {
    uint32_t h;
    asm("cvt.rna.tf32.f32 %0, %1;" : "=r"(h) : "f"(v));
    float lf = v - __uint_as_float(h);
    uint32_t l;
    asm("cvt.rna.tf32.f32 %0, %1;" : "=r"(l) : "f"(lf));
    hi = h; lo = l;
}

__device__ __forceinline__ void mma_tf32(float* c, const uint32_t* a, uint32_t b0, uint32_t b1) {
    asm volatile(
        "mma.sync.aligned.m16n8k8.row.col.f32.tf32.tf32.f32 "
        "{%0,%1,%2,%3},{%4,%5,%6,%7},{%8,%9},{%0,%1,%2,%3};"
        : "+f"(c[0]), "+f"(c[1]), "+f"(c[2]), "+f"(c[3])
        : "r"(a[0]), "r"(a[1]), "r"(a[2]), "r"(a[3]), "r"(b0), "r"(b1));
}

__global__ __launch_bounds__(256, 2) void gemm_tc_kernel(
    const float* __restrict__ A1, const float* __restrict__ W1,
    const float* __restrict__ A2, const float* __restrict__ W2,
    const float* __restrict__ bias, float* __restrict__ out,
    int M, int nparts, int do_relu, int do_stats)
{
    __shared__ float Ah[128][APAD], Al[128][APAD];
    __shared__ float Bh[KC][BPAD], Bl[KC][BPAD];
    __shared__ float csum[HID], csq[HID];

    int tid = threadIdx.x;
    int lane = tid & 31, warp = tid >> 5;
    int warpM = warp & 3;   // rows 32*warpM
    int warpN = warp >> 2;  // cols 64*warpN
    int g = lane >> 2, t4 = lane & 3;
    int rowBase = blockIdx.x * 128;

    float c[2][8][4];
#pragma unroll
    for (int mt = 0; mt < 2; mt++)
#pragma unroll
        for (int nt = 0; nt < 8; nt++)
#pragma unroll
            for (int i = 0; i < 4; i++) c[mt][nt][i] = 0.f;

    if (do_stats && tid < HID) { csum[tid] = 0.f; csq[tid] = 0.f; }

    for (int part = 0; part < nparts; part++) {
        const float* A = part ? A2 : A1;
        const float* W = part ? W2 : W1;
        for (int kc = 0; kc < HID; kc += KC) {
            __syncthreads();
            // stage A chunk [128 rows x 16 k] with hi/lo split
#pragma unroll
            for (int i = 0; i < 2; i++) {
                int id = tid + 256 * i;       // 0..511
                int row = id >> 2, k4 = id & 3;
                int grow = rowBase + row; if (grow >= M) grow = M - 1;
                float4 v = __ldg((const float4*)&A[grow * HID + kc + k4 * 4]);
                uint32_t hx, lx, hy, ly, hz, lz, hw, lw;
                tf32_split(v.x, hx, lx); tf32_split(v.y, hy, ly);
                tf32_split(v.z, hz, lz); tf32_split(v.w, hw, lw);
                *(float4*)&Ah[row][k4 * 4] = make_float4(
                    __uint_as_float(hx), __uint_as_float(hy),
                    __uint_as_float(hz), __uint_as_float(hw));
                *(float4*)&Al[row][k4 * 4] = make_float4(
                    __uint_as_float(lx), __uint_as_float(ly),
                    __uint_as_float(lz), __uint_as_float(lw));
            }
            // stage W chunk [16 k x 128 n] with hi/lo split
#pragma unroll
            for (int i = 0; i < 2; i++) {
                int id = tid + 256 * i;       // 0..511
                int k = id >> 5, n4 = id & 31;
                float4 v = __ldg((const float4*)&W[(kc + k) * HID + n4 * 4]);
                uint32_t hx, lx, hy, ly, hz, lz, hw, lw;
                tf32_split(v.x, hx, lx); tf32_split(v.y, hy, ly);
                tf32_split(v.z, hz, lz); tf32_split(v.w, hw, lw);
                *(float4*)&Bh[k][n4 * 4] = make_float4(
                    __uint_as_float(hx), __uint_as_float(hy),
                    __uint_as_float(hz), __uint_as_float(hw));
                *(float4*)&Bl[k][n4 * 4] = make_float4(
                    __uint_as_float(lx), __uint_as_float(ly),
                    __uint_as_float(lz), __uint_as_float(lw));
            }
            __syncthreads();
#pragma unroll
            for (int ks = 0; ks < KC / 8; ks++) {
                int k0 = ks * 8;
                uint32_t ah[2][4], al[2][4];
#pragma unroll
                for (int mt = 0; mt < 2; mt++) {
                    int r0 = warpM * 32 + mt * 16;
                    ah[mt][0] = __float_as_uint(Ah[r0 + g][k0 + t4]);
                    ah[mt][1] = __float_as_uint(Ah[r0 + 8 + g][k0 + t4]);
                    ah[mt][2] = __float_as_uint(Ah[r0 + g][k0 + 4 + t4]);
                    ah[mt][3] = __float_as_uint(Ah[r0 + 8 + g][k0 + 4 + t4]);
                    al[mt][0] = __float_as_uint(Al[r0 + g][k0 + t4]);
                    al[mt][1] = __float_as_uint(Al[r0 + 8 + g][k0 + t4]);
                    al[mt][2] = __float_as_uint(Al[r0 + g][k0 + 4 + t4]);
                    al[mt][3] = __float_as_uint(Al[r0 + 8 + g][k0 + 4 + t4]);
                }
#pragma unroll
                for (int nt = 0; nt < 8; nt++) {
                    int n0 = warpN * 64 + nt * 8;
                    uint32_t bh0 = __float_as_uint(Bh[k0 + t4][n0 + g]);
                    uint32_t bh1 = __float_as_uint(Bh[k0 + 4 + t4][n0 + g]);
                    uint32_t bl0 = __float_as_uint(Bl[k0 + t4][n0 + g]);
                    uint32_t bl1 = __float_as_uint(Bl[k0 + 4 + t4][n0 + g]);
#pragma unroll
                    for (int mt = 0; mt < 2; mt++) {
                        mma_tf32(c[mt][nt], ah[mt], bh0, bh1);  // hi*hi
                        mma_tf32(c[mt][nt], al[mt], bh0, bh1);  // lo*hi
                        mma_tf32(c[mt][nt], ah[mt], bl0, bl1);  // hi*lo
                    }
                }
            }
        }
    }

    // ---- epilogue: bias (+relu) (+BN stats) + store ----
#pragma unroll
    for (int nt = 0; nt < 8; nt++) {
        int n0 = warpN * 64 + nt * 8 + 2 * t4;
        float b0v = __ldg(&bias[n0]);
        float b1v = __ldg(&bias[n0 + 1]);
        float lsum0 = 0.f, lsum1 = 0.f, lsq0 = 0.f, lsq1 = 0.f;
#pragma unroll
        for (int mt = 0; mt < 2; mt++) {
            int row0 = rowBase + warpM * 32 + mt * 16 + g;
            float v00 = c[mt][nt][0] + b0v, v01 = c[mt][nt][1] + b1v;
            float v10 = c[mt][nt][2] + b0v, v11 = c[mt][nt][3] + b1v;
            if (do_relu) {
                v00 = fmaxf(v00, 0.f); v01 = fmaxf(v01, 0.f);
                v10 = fmaxf(v10, 0.f); v11 = fmaxf(v11, 0.f);
            }
            if (row0 < M) {
                *(float2*)&out[row0 * HID + n0] = make_float2(v00, v01);
                lsum0 += v00; lsum1 += v01; lsq0 += v00 * v00; lsq1 += v01 * v01;
            }
            if (row0 + 8 < M) {
                *(float2*)&out[(row0 + 8) * HID + n0] = make_float2(v10, v11);
                lsum0 += v10; lsum1 += v11; lsq0 += v10 * v10; lsq1 += v11 * v11;
            }
        }
        if (do_stats) {
            atomicAdd(&csum[n0], lsum0);
            atomicAdd(&csum[n0 + 1], lsum1);
            atomicAdd(&csq[n0], lsq0);
            atomicAdd(&csq[n0 + 1], lsq1);
        }
    }
    if (do_stats) {
        __syncthreads();
        if (tid < HID) {
            atomicAdd(&g_bnsum[tid], csum[tid]);
            atomicAdd(&g_bnsq[tid], csq[tid]);
        }
    }
}

// ---------------- BN finalize ----------------
__global__ void bn_finalize_kernel(const float* __restrict__ gamma, const float* __restrict__ beta) {
    int c = threadIdx.x;
    const float invn = 1.0f / (float)N_NODES;
    float m = g_bnsum[c] * invn;
    float var = g_bnsq[c] * invn - m * m;
    var = fmaxf(var, 0.f);
    float s = gamma[c] * rsqrtf(var + BN_EPS);
    g_scale[c] = s;
    g_shift[c] = beta[c] - m * s;
    g_bnsum[c] = 0.f;
    g_bnsq[c] = 0.f;
}

// ---------------- pooling: batch is sorted, block per graph ----------------
__device__ __forceinline__ int lbound(const int* a, int n, int v) {
    int lo = 0, hi = n;
    while (lo < hi) {
        int mid = (lo + hi) >> 1;
        if (a[mid] < v) lo = mid + 1; else hi = mid;
    }
    return lo;
}

__global__ void pool_kernel(const float* __restrict__ hraw,
                            const int* __restrict__ batch,
                            float* __restrict__ out) {
    int gg = blockIdx.x;
    int c = threadIdx.x;
    int start = lbound(batch, N_NODES, gg);
    int end = lbound(batch, N_NODES, gg + 1);
    int cnt = end - start;
    float sc = g_scale[c], sh = g_shift[c];
    float s = 0.f;
    for (int i = start; i < end; i++) {
        float v = fmaf(hraw[i * HID + c], sc, sh);
        s += fmaxf(v, 0.f);
    }
    out[gg * HID + c] = s / fmaxf((float)cnt, 1.f);
}

// ---------------- launch ----------------
extern "C" void kernel_launch(void* const* d_in, const int* in_sizes, int n_in,
                              void* d_out, int out_size) {
    (void)in_sizes; (void)n_in; (void)out_size;
    const float* x       = (const float*)d_in[0];
    const int*   eidx    = (const int*)d_in[1];
    const int*   batch   = (const int*)d_in[2];
    const float* gin_w1  = (const float*)d_in[3];
    const float* gin_b1  = (const float*)d_in[4];
    const float* gin_w2  = (const float*)d_in[5];
    const float* gin_b2  = (const float*)d_in[6];
    const float* sage_wl = (const float*)d_in[7];
    const float* sage_bl = (const float*)d_in[8];
    const float* sage_wr = (const float*)d_in[9];
    const float* bn_g    = (const float*)d_in[10];
    const float* bn_b    = (const float*)d_in[11];
    float* out = (float*)d_out;

    const int* src = eidx;
    const int* dst = eidx + N_EDGES;

    float *p_h0, *p_t1, *p_h1, *p_hbn, *p_ng;
    cudaGetSymbolAddress((void**)&p_h0, g_h0);
    cudaGetSymbolAddress((void**)&p_t1, g_t1);
    cudaGetSymbolAddress((void**)&p_h1, g_h1);
    cudaGetSymbolAddress((void**)&p_hbn, g_hbn);
    cudaGetSymbolAddress((void**)&p_ng, g_neigh);

    const int M = N_NODES;
    const int gemmGrid = (M + 127) / 128;            // 391
    const int aggGrid = (N_NODES * 32 + 255) / 256;  // warp per node
    const int edgeGrid = (N_EDGES + 255) / 256;

    // CSR build (degrees reused for all layers)
    zero_init_kernel<<<(N_NODES + 255) / 256, 256>>>();
    hist_kernel<<<edgeGrid, 256>>>(dst);
    scan_kernel<<<1, 1024>>>();
    scatter_kernel<<<edgeGrid, 256>>>(src, dst);

    // Layer 0: GIN
    gin_agg_kernel<<<aggGrid, 256>>>(x);
    gemm_tc_kernel<<<gemmGrid, 256>>>(p_h0, gin_w1, p_h0, gin_w1, gin_b1, p_t1, M, 1, 1, 0);
    gemm_tc_kernel<<<gemmGrid, 256>>>(p_t1, gin_w2, p_t1, gin_w2, gin_b2, p_h1, M, 1, 0, 1);
    bn_finalize_kernel<<<1, HID>>>(bn_g + 0 * HID, bn_b + 0 * HID);

    // SAGE layer 0
    sage_agg_kernel<<<aggGrid, 256>>>(p_h1, p_hbn, p_ng);
    gemm_tc_kernel<<<gemmGrid, 256>>>(p_ng, sage_wl, p_hbn, sage_wr, sage_bl, p_h0, M, 2, 0, 1);
    bn_finalize_kernel<<<1, HID>>>(bn_g + 1 * HID, bn_b + 1 * HID);

    // SAGE layer 1
    sage_agg_kernel<<<aggGrid, 256>>>(p_h0, p_hbn, p_ng);
    gemm_tc_kernel<<<gemmGrid, 256>>>(p_ng, sage_wl + HID * HID, p_hbn, sage_wr + HID * HID,
                                      sage_bl + HID, p_t1, M, 2, 0, 1);
    bn_finalize_kernel<<<1, HID>>>(bn_g + 2 * HID, bn_b + 2 * HID);

    // global mean pool (batch sorted)
    pool_kernel<<<N_GRAPHS, HID>>>(p_t1, batch, out);
}

// round 3
// speedup vs baseline: 1.2578x; 1.2578x over previous
#include <cuda_runtime.h>
#include <cuda_bf16.h>
#include <cstdint>

#define N_NODES 50000
#define N_EDGES 600000
#define HID     128
#define N_GRAPHS 512
#define BN_EPS  1e-5f

// ---------------- scratch (static device allocations; no cudaMalloc) ----------------
__device__ float g_h0[N_NODES * HID];
__device__ float g_h1[N_NODES * HID];
__device__ float g_hbn[N_NODES * HID];
__device__ float g_neigh[N_NODES * HID];
__device__ float g_t2[N_NODES * HID];

__device__ int   g_deg[N_NODES];
__device__ int   g_off[N_NODES + 1];
__device__ int   g_cur[N_NODES];
__device__ int   g_csr[N_EDGES];
__device__ float g_invdeg[N_NODES];

__device__ float g_bnsum[HID];
__device__ float g_bnsq[HID];
__device__ float g_scale[HID];
__device__ float g_shift[HID];

// ---------------- helpers ----------------
__device__ __forceinline__ unsigned long long pack_dup(float x) {
    unsigned long long d;
    asm("mov.b64 %0,{%1,%1};" : "=l"(d) : "f"(x));
    return d;
}

// transposed A layout: element (k, row) at k*132 + 4*(k>>2) + row
// -> STS banks (20*kq + 4c + row) % 32 : conflict-free; rows stay 16B aligned.
#define AS_IDX(k, row) ((k) * 132 + 4 * ((k) >> 2) + (row))
#define AS_SIZE 4256
// B layout: element (k, n) at k*132 + n
#define BS_IDX(k, n) ((k) * 132 + (n))
#define BS_SIZE 4224
#define TS_SIZE 17024

// ---------------- setup kernels ----------------
__global__ void zero_init_kernel() {
    int i = blockIdx.x * blockDim.x + threadIdx.x;
    if (i < N_NODES) g_deg[i] = 0;
    if (i < HID) { g_bnsum[i] = 0.f; g_bnsq[i] = 0.f; }
}

__global__ void hist_kernel(const int* __restrict__ dst) {
    int e = blockIdx.x * blockDim.x + threadIdx.x;
    if (e < N_EDGES) atomicAdd(&g_deg[dst[e]], 1);
}

__global__ void scan_kernel() {
    __shared__ int sh[1024];
    const int CH = (N_NODES + 1023) / 1024;  // 49
    int t = threadIdx.x;
    int base = t * CH;
    int tsum = 0;
    for (int i = 0; i < CH; i++) {
        int idx = base + i;
        if (idx < N_NODES) tsum += g_deg[idx];
    }
    sh[t] = tsum;
    __syncthreads();
    for (int off = 1; off < 1024; off <<= 1) {
        int v = (t >= off) ? sh[t - off] : 0;
        __syncthreads();
        sh[t] += v;
        __syncthreads();
    }
    int run = sh[t] - tsum;
    for (int i = 0; i < CH; i++) {
        int idx = base + i;
        if (idx < N_NODES) {
            int d = g_deg[idx];
            g_off[idx] = run;
            g_cur[idx] = run;
            g_invdeg[idx] = 1.0f / (float)max(d, 1);
            run += d;
        }
    }
    if (t == 1023) g_off[N_NODES] = sh[1023];
}

__global__ void scatter_kernel(const int* __restrict__ src, const int* __restrict__ dst) {
    int e = blockIdx.x * blockDim.x + threadIdx.x;
    if (e < N_EDGES) {
        int d = dst[e];
        int p = atomicAdd(&g_cur[d], 1);
        g_csr[p] = src[e];
    }
}

// ---------------- aggregation kernels (warp per node) ----------------
__global__ void gin_agg_kernel(const float* __restrict__ x) {
    int w = (blockIdx.x * blockDim.x + threadIdx.x) >> 5;
    int lane = threadIdx.x & 31;
    if (w >= N_NODES) return;
    const float4* x4 = (const float4*)x;
    float4 acc = __ldg(&x4[w * 32 + lane]);
    int e = g_off[w], end = g_off[w + 1];
    for (; e + 4 <= end; e += 4) {
        int s0 = g_csr[e + 0], s1 = g_csr[e + 1], s2 = g_csr[e + 2], s3 = g_csr[e + 3];
        float4 v0 = __ldg(&x4[s0 * 32 + lane]);
        float4 v1 = __ldg(&x4[s1 * 32 + lane]);
        float4 v2 = __ldg(&x4[s2 * 32 + lane]);
        float4 v3 = __ldg(&x4[s3 * 32 + lane]);
        acc.x += v0.x + v1.x + v2.x + v3.x;
        acc.y += v0.y + v1.y + v2.y + v3.y;
        acc.z += v0.z + v1.z + v2.z + v3.z;
        acc.w += v0.w + v1.w + v2.w + v3.w;
    }
    for (; e < end; e++) {
        int s0 = g_csr[e];
        float4 v0 = __ldg(&x4[s0 * 32 + lane]);
        acc.x += v0.x; acc.y += v0.y; acc.z += v0.z; acc.w += v0.w;
    }
    ((float4*)g_h0)[w * 32 + lane] = acc;
}

__device__ __forceinline__ float4 bn_relu4(float4 h, float4 sc, float4 sh) {
    float4 r;
    r.x = fmaxf(fmaf(h.x, sc.x, sh.x), 0.f);
    r.y = fmaxf(fmaf(h.y, sc.y, sh.y), 0.f);
    r.z = fmaxf(fmaf(h.z, sc.z, sh.z), 0.f);
    r.w = fmaxf(fmaf(h.w, sc.w, sh.w), 0.f);
    return r;
}

__global__ void sage_agg_kernel(const float* __restrict__ hraw,
                                float* __restrict__ hbn,
                                float* __restrict__ neigh) {
    int w = (blockIdx.x * blockDim.x + threadIdx.x) >> 5;
    int lane = threadIdx.x & 31;
    if (w >= N_NODES) return;
    float4 sc = *(const float4*)&g_scale[lane * 4];
    float4 sh = *(const float4*)&g_shift[lane * 4];
    const float4* h4 = (const float4*)hraw;

    float4 self = bn_relu4(__ldg(&h4[w * 32 + lane]), sc, sh);
    ((float4*)hbn)[w * 32 + lane] = self;

    float4 acc = make_float4(0.f, 0.f, 0.f, 0.f);
    int e = g_off[w], end = g_off[w + 1];
    for (; e + 4 <= end; e += 4) {
        int s0 = g_csr[e + 0], s1 = g_csr[e + 1], s2 = g_csr[e + 2], s3 = g_csr[e + 3];
        float4 v0 = bn_relu4(__ldg(&h4[s0 * 32 + lane]), sc, sh);
        float4 v1 = bn_relu4(__ldg(&h4[s1 * 32 + lane]), sc, sh);
        float4 v2 = bn_relu4(__ldg(&h4[s2 * 32 + lane]), sc, sh);
        float4 v3 = bn_relu4(__ldg(&h4[s3 * 32 + lane]), sc, sh);
        acc.x += v0.x + v1.x + v2.x + v3.x;
        acc.y += v0.y + v1.y + v2.y + v3.y;
        acc.z += v0.z + v1.z + v2.z + v3.z;
        acc.w += v0.w + v1.w + v2.w + v3.w;
    }
    for (; e < end; e++) {
        int s0 = g_csr[e];
        float4 v0 = bn_relu4(__ldg(&h4[s0 * 32 + lane]), sc, sh);
        acc.x += v0.x; acc.y += v0.y; acc.z += v0.z; acc.w += v0.w;
    }
    float id = g_invdeg[w];
    acc.x *= id; acc.y *= id; acc.z *= id; acc.w *= id;
    ((float4*)neigh)[w * 32 + lane] = acc;
}

// ---------------- shared GEMM building blocks ----------------
// stage A chunk [128 rows x 32 k] transposed into Asf (conflict-free)
__device__ __forceinline__ void stage_A(float* Asf, const float* __restrict__ A,
                                        int rowBase, int kc, int M, int tid) {
#pragma unroll
    for (int i = 0; i < 4; i++) {
        int f = tid + 256 * i;
        int row = f >> 3, kq = f & 7;
        int grow = rowBase + row; if (grow >= M) grow = M - 1;
        float4 v = __ldg((const float4*)&A[grow * HID + kc + kq * 4]);
        int k0 = kq * 4;
        Asf[AS_IDX(k0 + 0, row)] = v.x;
        Asf[AS_IDX(k0 + 1, row)] = v.y;
        Asf[AS_IDX(k0 + 2, row)] = v.z;
        Asf[AS_IDX(k0 + 3, row)] = v.w;
    }
}

// stage W chunk [32 k x 128 n] into Bsf
__device__ __forceinline__ void stage_B(float* Bsf, const float* __restrict__ W,
                                        int kc, int tid) {
#pragma unroll
    for (int i = 0; i < 4; i++) {
        int f = tid + 256 * i;
        int k = f >> 5, n4 = f & 31;
        float4 v = __ldg((const float4*)&W[(kc + k) * HID + n4 * 4]);
        *(float4*)&Bsf[BS_IDX(k, n4 * 4)] = v;
    }
}

// 32-k compute over staged chunk (A-frag addresses use AS_IDX-compatible bases)
__device__ __forceinline__ void compute_chunk(const float* __restrict__ Afrag,
                                              const float* __restrict__ Bsf,
                                              int trow, int tcol,
                                              unsigned long long acc[8][4]) {
#pragma unroll 8
    for (int k = 0; k < 32; k++) {
        const float* ar = &Afrag[k * 132 + 4 * (k >> 2) + trow * 16];
        unsigned long long a[8];
        ulonglong2 t;
        t = *(const ulonglong2*)(ar + 0);  a[0] = t.x; a[1] = t.y;
        t = *(const ulonglong2*)(ar + 4);  a[2] = t.x; a[3] = t.y;
        t = *(const ulonglong2*)(ar + 8);  a[4] = t.x; a[5] = t.y;
        t = *(const ulonglong2*)(ar + 12); a[6] = t.x; a[7] = t.y;
        float4 b4 = *(const float4*)&Bsf[BS_IDX(k, tcol * 4)];
        unsigned long long bb0 = pack_dup(b4.x);
        unsigned long long bb1 = pack_dup(b4.y);
        unsigned long long bb2 = pack_dup(b4.z);
        unsigned long long bb3 = pack_dup(b4.w);
#pragma unroll
        for (int r = 0; r < 8; r++) {
            asm("fma.rn.f32x2 %0,%1,%2,%0;" : "+l"(acc[r][0]) : "l"(a[r]), "l"(bb0));
            asm("fma.rn.f32x2 %0,%1,%2,%0;" : "+l"(acc[r][1]) : "l"(a[r]), "l"(bb1));
            asm("fma.rn.f32x2 %0,%1,%2,%0;" : "+l"(acc[r][2]) : "l"(a[r]), "l"(bb2));
            asm("fma.rn.f32x2 %0,%1,%2,%0;" : "+l"(acc[r][3]) : "l"(a[r]), "l"(bb3));
        }
    }
}

// epilogue: bias (+relu) (+BN stats) + store
__device__ __forceinline__ void gemm_epilogue(unsigned long long acc[8][4],
                                              const float* __restrict__ bias,
                                              float* __restrict__ out,
                                              float* csum, float* csq,
                                              int rowBase, int trow, int tcol,
                                              int M, int do_relu, int do_stats, int tid) {
    float4 bias4 = __ldg((const float4*)&bias[tcol * 4]);
    float bv[4] = { bias4.x, bias4.y, bias4.z, bias4.w };
    float lsum[4] = {0, 0, 0, 0}, lsq[4] = {0, 0, 0, 0};
#pragma unroll
    for (int r = 0; r < 8; r++) {
        float vlo[4], vhi[4];
#pragma unroll
        for (int c = 0; c < 4; c++) {
            unsigned long long u = acc[r][c];
            vlo[c] = __uint_as_float((unsigned)u) + bv[c];
            vhi[c] = __uint_as_float((unsigned)(u >> 32)) + bv[c];
            if (do_relu) { vlo[c] = fmaxf(vlo[c], 0.f); vhi[c] = fmaxf(vhi[c], 0.f); }
        }
        int row0 = rowBase + trow * 16 + 2 * r;
        if (row0 < M) {
            *(float4*)&out[row0 * HID + tcol * 4] = make_float4(vlo[0], vlo[1], vlo[2], vlo[3]);
            if (do_stats)
#pragma unroll
                for (int c = 0; c < 4; c++) { lsum[c] += vlo[c]; lsq[c] += vlo[c] * vlo[c]; }
        }
        if (row0 + 1 < M) {
            *(float4*)&out[(row0 + 1) * HID + tcol * 4] = make_float4(vhi[0], vhi[1], vhi[2], vhi[3]);
            if (do_stats)
#pragma unroll
                for (int c = 0; c < 4; c++) { lsum[c] += vhi[c]; lsq[c] += vhi[c] * vhi[c]; }
        }
    }
    if (do_stats) {
#pragma unroll
        for (int c = 0; c < 4; c++) {
            atomicAdd(&csum[tcol * 4 + c], lsum[c]);
            atomicAdd(&csq[tcol * 4 + c], lsq[c]);
        }
        __syncthreads();
        if (tid < HID) {
            atomicAdd(&g_bnsum[tid], csum[tid]);
            atomicAdd(&g_bnsq[tid], csq[tid]);
        }
    }
}

// ---------------- SAGE GEMM: out = A1@W1 + A2@W2 + bias, stats ----------------
__global__ __launch_bounds__(256, 2) void gemm_sage_kernel(
    const float* __restrict__ A1, const float* __restrict__ W1,
    const float* __restrict__ A2, const float* __restrict__ W2,
    const float* __restrict__ bias, float* __restrict__ out, int M)
{
    __shared__ __align__(16) float Asf[AS_SIZE];
    __shared__ __align__(16) float Bsf[BS_SIZE];
    __shared__ float csum[HID], csq[HID];

    int tid = threadIdx.x;
    int tcol = tid & 31;
    int trow = tid >> 5;
    int rowBase = blockIdx.x * 128;

    unsigned long long acc[8][4];
#pragma unroll
    for (int r = 0; r < 8; r++)
#pragma unroll
        for (int c = 0; c < 4; c++) acc[r][c] = 0ULL;
    if (tid < HID) { csum[tid] = 0.f; csq[tid] = 0.f; }

    for (int part = 0; part < 2; part++) {
        const float* A = part ? A2 : A1;
        const float* W = part ? W2 : W1;
        for (int kc = 0; kc < HID; kc += 32) {
            __syncthreads();
            stage_A(Asf, A, rowBase, kc, M, tid);
            stage_B(Bsf, W, kc, tid);
            __syncthreads();
            compute_chunk(Asf, Bsf, trow, tcol, acc);
        }
    }
    gemm_epilogue(acc, bias, out, csum, csq, rowBase, trow, tcol, M, 0, 1, tid);
}

// ---------------- fused GIN MLP: h1 = relu(A@W1+b1)@W2 + b2 (+stats) ----------------
__global__ __launch_bounds__(256, 2) void gin_mlp_fused_kernel(
    const float* __restrict__ A, const float* __restrict__ W1, const float* __restrict__ b1,
    const float* __restrict__ W2, const float* __restrict__ b2,
    float* __restrict__ out, int M)
{
    extern __shared__ __align__(16) float dyn[];
    float* Asf = dyn;
    float* Bsf = dyn + AS_SIZE;
    float* Tsf = dyn + AS_SIZE + BS_SIZE;
    __shared__ float csum[HID], csq[HID];

    int tid = threadIdx.x;
    int tcol = tid & 31;
    int trow = tid >> 5;
    int rowBase = blockIdx.x * 128;

    unsigned long long acc[8][4];
#pragma unroll
    for (int r = 0; r < 8; r++)
#pragma unroll
        for (int c = 0; c < 4; c++) acc[r][c] = 0ULL;
    if (tid < HID) { csum[tid] = 0.f; csq[tid] = 0.f; }

    // ---- phase 1: t = relu(A @ W1 + b1) ----
    for (int kc = 0; kc < HID; kc += 32) {
        __syncthreads();
        stage_A(Asf, A, rowBase, kc, M, tid);
        stage_B(Bsf, W1, kc, tid);
        __syncthreads();
        compute_chunk(Asf, Bsf, trow, tcol, acc);
    }

    // write t into Tsf in transposed A-frag layout; reset acc
    {
        float4 bias4 = __ldg((const float4*)&b1[tcol * 4]);
        float bv[4] = { bias4.x, bias4.y, bias4.z, bias4.w };
        __syncthreads();  // all compute reads of Asf/Bsf done (Tsf untouched yet anyway)
#pragma unroll
        for (int r = 0; r < 8; r++) {
            int row0 = trow * 16 + 2 * r;
#pragma unroll
            for (int c = 0; c < 4; c++) {
                unsigned long long u = acc[r][c];
                float vlo = fmaxf(__uint_as_float((unsigned)u) + bv[c], 0.f);
                float vhi = fmaxf(__uint_as_float((unsigned)(u >> 32)) + bv[c], 0.f);
                int col = tcol * 4 + c;
                Tsf[AS_IDX(col, row0)] = vlo;
                Tsf[AS_IDX(col, row0 + 1)] = vhi;
                acc[r][c] = 0ULL;
            }
        }
    }
    __syncthreads();

    // ---- phase 2: out = t @ W2 + b2, with BN stats ----
    for (int kc = 0; kc < HID; kc += 32) {
        __syncthreads();
        stage_B(Bsf, W2, kc, tid);
        __syncthreads();
        // A-frags come from Tsf at column offset kc
        compute_chunk(&Tsf[AS_IDX(kc, 0)], Bsf, trow, tcol, acc);
    }
    gemm_epilogue(acc, b2, out, csum, csq, rowBase, trow, tcol, M, 0, 1, tid);
}

// ---------------- BN finalize ----------------
__global__ void bn_finalize_kernel(const float* __restrict__ gamma, const float* __restrict__ beta) {
    int c = threadIdx.x;
    const float invn = 1.0f / (float)N_NODES;
    float m = g_bnsum[c] * invn;
    float var = g_bnsq[c] * invn - m * m;
    var = fmaxf(var, 0.f);
    float s = gamma[c] * rsqrtf(var + BN_EPS);
    g_scale[c] = s;
    g_shift[c] = beta[c] - m * s;
    g_bnsum[c] = 0.f;
    g_bnsq[c] = 0.f;
}

// ---------------- pooling: batch is sorted, block per graph ----------------
__device__ __forceinline__ int lbound(const int* a, int n, int v) {
    int lo = 0, hi = n;
    while (lo < hi) {
        int mid = (lo + hi) >> 1;
        if (a[mid] < v) lo = mid + 1; else hi = mid;
    }
    return lo;
}

__global__ void pool_kernel(const float* __restrict__ hraw,
                            const int* __restrict__ batch,
                            float* __restrict__ out) {
    int gg = blockIdx.x;
    int c = threadIdx.x;
    int start = lbound(batch, N_NODES, gg);
    int end = lbound(batch, N_NODES, gg + 1);
    int cnt = end - start;
    float sc = g_scale[c], sh = g_shift[c];
    float s = 0.f;
    for (int i = start; i < end; i++) {
        float v = fmaf(hraw[i * HID + c], sc, sh);
        s += fmaxf(v, 0.f);
    }
    out[gg * HID + c] = s / fmaxf((float)cnt, 1.f);
}

// ---------------- launch ----------------
extern "C" void kernel_launch(void* const* d_in, const int* in_sizes, int n_in,
                              void* d_out, int out_size) {
    (void)in_sizes; (void)n_in; (void)out_size;
    const float* x       = (const float*)d_in[0];
    const int*   eidx    = (const int*)d_in[1];
    const int*   batch   = (const int*)d_in[2];
    const float* gin_w1  = (const float*)d_in[3];
    const float* gin_b1  = (const float*)d_in[4];
    const float* gin_w2  = (const float*)d_in[5];
    const float* gin_b2  = (const float*)d_in[6];
    const float* sage_wl = (const float*)d_in[7];
    const float* sage_bl = (const float*)d_in[8];
    const float* sage_wr = (const float*)d_in[9];
    const float* bn_g    = (const float*)d_in[10];
    const float* bn_b    = (const float*)d_in[11];
    float* out = (float*)d_out;

    const int* src = eidx;
    const int* dst = eidx + N_EDGES;

    float *p_h0, *p_h1, *p_hbn, *p_ng, *p_t2;
    cudaGetSymbolAddress((void**)&p_h0, g_h0);
    cudaGetSymbolAddress((void**)&p_h1, g_h1);
    cudaGetSymbolAddress((void**)&p_hbn, g_hbn);
    cudaGetSymbolAddress((void**)&p_ng, g_neigh);
    cudaGetSymbolAddress((void**)&p_t2, g_t2);

    const int M = N_NODES;
    const int gemmGrid = (M + 127) / 128;            // 391
    const int aggGrid = (N_NODES * 32 + 255) / 256;  // warp per node
    const int edgeGrid = (N_EDGES + 255) / 256;

    const int fusedSmem = (AS_SIZE + BS_SIZE + TS_SIZE) * 4;  // ~102KB
    static int attr_set = 0;
    if (!attr_set) {
        cudaFuncSetAttribute(gin_mlp_fused_kernel,
                             cudaFuncAttributeMaxDynamicSharedMemorySize, fusedSmem);
        attr_set = 1;
    }

    // CSR build
    zero_init_kernel<<<(N_NODES + 255) / 256, 256>>>();
    hist_kernel<<<edgeGrid, 256>>>(dst);
    scan_kernel<<<1, 1024>>>();
    scatter_kernel<<<edgeGrid, 256>>>(src, dst);

    // Layer 0: GIN (fused MLP)
    gin_agg_kernel<<<aggGrid, 256>>>(x);
    gin_mlp_fused_kernel<<<gemmGrid, 256, fusedSmem>>>(p_h0, gin_w1, gin_b1, gin_w2, gin_b2, p_h1, M);
    bn_finalize_kernel<<<1, HID>>>(bn_g + 0 * HID, bn_b + 0 * HID);

    // SAGE layer 0
    sage_agg_kernel<<<aggGrid, 256>>>(p_h1, p_hbn, p_ng);
    gemm_sage_kernel<<<gemmGrid, 256>>>(p_ng, sage_wl, p_hbn, sage_wr, sage_bl, p_h0, M);
    bn_finalize_kernel<<<1, HID>>>(bn_g + 1 * HID, bn_b + 1 * HID);

    // SAGE layer 1
    sage_agg_kernel<<<aggGrid, 256>>>(p_h0, p_hbn, p_ng);
    gemm_sage_kernel<<<gemmGrid, 256>>>(p_ng, sage_wl + HID * HID, p_hbn, sage_wr + HID * HID,
                                        sage_bl + HID, p_t2, M);
    bn_finalize_kernel<<<1, HID>>>(bn_g + 2 * HID, bn_b + 2 * HID);

    // global mean pool (batch sorted)
    pool_kernel<<<N_GRAPHS, HID>>>(p_t2, batch, out);
}